// round 1
// baseline (speedup 1.0000x reference)
#include <cuda_runtime.h>
#include <math.h>

// Problem constants
#define BDIM   4
#define TDIM   2048
#define CDIM   1024
#define HEADS  16
#define HD     64
#define FFDIM  4096
#define BT     8192            // B*T rows
#define QKVW   3072            // 3*C

// ---------------------------------------------------------------------------
// Scratch (no allocations allowed — __device__ globals)
// ---------------------------------------------------------------------------
__device__ float g_ln [BT * CDIM];          // layernorm output (reused ln1/ln2)
__device__ float g_qkv[BT * QKVW];          // qkv projection
__device__ float g_y  [BT * CDIM];          // attention output (pre o-proj)
__device__ float g_x2 [BT * CDIM];          // x + attn (residual stream 2)
__device__ float g_h  [BT * FFDIM];         // gelu(fc) activations

// ---------------------------------------------------------------------------
// Packed f32x2 helpers (Blackwell 2x fp32 pipe; FFMA2 only reachable via PTX)
// ---------------------------------------------------------------------------
__device__ __forceinline__ unsigned long long pack2(float lo, float hi) {
    unsigned long long r;
    asm("mov.b64 %0, {%1, %2};" : "=l"(r)
        : "r"(__float_as_uint(lo)), "r"(__float_as_uint(hi)));
    return r;
}
__device__ __forceinline__ void fma2(unsigned long long& d,
                                     unsigned long long a,
                                     unsigned long long b) {
    asm("fma.rn.f32x2 %0, %1, %2, %0;" : "+l"(d) : "l"(a), "l"(b));
}
__device__ __forceinline__ float2 unpack2(unsigned long long v) {
    unsigned int lo, hi;
    asm("mov.b64 {%0, %1}, %2;" : "=r"(lo), "=r"(hi) : "l"(v));
    return make_float2(__uint_as_float(lo), __uint_as_float(hi));
}

__device__ __forceinline__ float gelu_f(float v) {
    return 0.5f * v * (1.0f + erff(v * 0.70710678118654752f));
}

// ---------------------------------------------------------------------------
// LayerNorm: one block per row, C=1024, 256 threads x float4
// ---------------------------------------------------------------------------
__global__ __launch_bounds__(256)
void ln_kernel(const float* __restrict__ x, const float* __restrict__ g,
               float* __restrict__ y)
{
    const int row = blockIdx.x;
    const int tid = threadIdx.x;
    const float4 v = ((const float4*)(x + (size_t)row * CDIM))[tid];
    float s  = v.x + v.y + v.z + v.w;
    float ss = v.x * v.x + v.y * v.y + v.z * v.z + v.w * v.w;
#pragma unroll
    for (int o = 16; o > 0; o >>= 1) {
        s  += __shfl_xor_sync(0xffffffffu, s,  o);
        ss += __shfl_xor_sync(0xffffffffu, ss, o);
    }
    __shared__ float rs[8], rss[8];
    const int w = tid >> 5, lane = tid & 31;
    if (lane == 0) { rs[w] = s; rss[w] = ss; }
    __syncthreads();
    if (tid == 0) {
        float a = 0.f, b = 0.f;
#pragma unroll
        for (int i = 0; i < 8; i++) { a += rs[i]; b += rss[i]; }
        const float mean = a * (1.0f / CDIM);
        const float var  = b * (1.0f / CDIM) - mean * mean;
        rs[0]  = mean;
        rss[0] = rsqrtf(var + 1e-5f);
    }
    __syncthreads();
    const float mean = rs[0], rstd = rss[0];
    const float4 gv = ((const float4*)g)[tid];
    float4 o4;
    o4.x = (v.x - mean) * rstd * gv.x;
    o4.y = (v.y - mean) * rstd * gv.y;
    o4.z = (v.z - mean) * rstd * gv.z;
    o4.w = (v.w - mean) * rstd * gv.w;
    ((float4*)(y + (size_t)row * CDIM))[tid] = o4;
}

// ---------------------------------------------------------------------------
// SGEMM NT: C[m,n] = sum_k A[m,k] * B[n,k]  (A: [M,K] row-major, B: [N,K])
// 128x128 block tile, BK=8, 256 threads, 8x8 per thread, packed f32x2 FMA,
// register prefetch of next k-tile.
// EPI: 0 = none, 1 = out = acc + res, 2 = out = gelu(acc)
// M,N multiples of 128; K multiple of 8.
// ---------------------------------------------------------------------------
template <int EPI>
__global__ __launch_bounds__(256)
void sgemm_nt(const float* __restrict__ A, const float* __restrict__ B,
              const float* __restrict__ res, float* __restrict__ C,
              int M, int N, int K)
{
    __shared__ float As[8][128];
    __shared__ float Bs[8][128];

    const int tid  = threadIdx.x;
    const int bm   = blockIdx.y << 7;
    const int bn   = blockIdx.x << 7;
    const int lrow = tid >> 1;           // 0..127
    const int lcol = (tid & 1) << 2;     // 0 or 4
    const int tx   = tid & 15;           // col octet
    const int ty   = tid >> 4;           // row octet

    const float* Ap = A + (size_t)(bm + lrow) * K + lcol;
    const float* Bp = B + (size_t)(bn + lrow) * K + lcol;

    unsigned long long acc[8][4];
#pragma unroll
    for (int i = 0; i < 8; i++)
#pragma unroll
        for (int j = 0; j < 4; j++) acc[i][j] = 0ull;

    float4 av = *(const float4*)Ap;
    float4 bv = *(const float4*)Bp;

    for (int k0 = 0; k0 < K; k0 += 8) {
        As[lcol + 0][lrow] = av.x; As[lcol + 1][lrow] = av.y;
        As[lcol + 2][lrow] = av.z; As[lcol + 3][lrow] = av.w;
        Bs[lcol + 0][lrow] = bv.x; Bs[lcol + 1][lrow] = bv.y;
        Bs[lcol + 2][lrow] = bv.z; Bs[lcol + 3][lrow] = bv.w;
        __syncthreads();
        if (k0 + 8 < K) {                 // prefetch next tile into registers
            av = *(const float4*)(Ap + k0 + 8);
            bv = *(const float4*)(Bp + k0 + 8);
        }
#pragma unroll
        for (int kk = 0; kk < 8; kk++) {
            const float4 a0 = *(const float4*)&As[kk][ty * 8];
            const float4 a1 = *(const float4*)&As[kk][ty * 8 + 4];
            const unsigned long long* brow =
                (const unsigned long long*)&Bs[kk][tx * 8];
            const unsigned long long rb0 = brow[0], rb1 = brow[1],
                                     rb2 = brow[2], rb3 = brow[3];
            const float ra[8] = {a0.x, a0.y, a0.z, a0.w,
                                 a1.x, a1.y, a1.z, a1.w};
#pragma unroll
            for (int i = 0; i < 8; i++) {
                const unsigned long long ai = pack2(ra[i], ra[i]);
                fma2(acc[i][0], ai, rb0);
                fma2(acc[i][1], ai, rb1);
                fma2(acc[i][2], ai, rb2);
                fma2(acc[i][3], ai, rb3);
            }
        }
        __syncthreads();
    }

#pragma unroll
    for (int i = 0; i < 8; i++) {
        const int m = bm + ty * 8 + i;
#pragma unroll
        for (int j2 = 0; j2 < 4; j2++) {
            float2 v = unpack2(acc[i][j2]);
            const int n = bn + tx * 8 + j2 * 2;
            const size_t idx = (size_t)m * N + n;
            if (EPI == 1) { v.x += res[idx]; v.y += res[idx + 1]; }
            if (EPI == 2) { v.x = gelu_f(v.x); v.y = gelu_f(v.y); }
            *(float2*)(C + idx) = v;
        }
    }
}

// ---------------------------------------------------------------------------
// Flash attention (fp32, causal). Grid: (T/64, B*H). Block: 256 threads.
// Thread (ty = tid/4) owns query row ty; tx = tid%4 owns 16 of 64 cols.
// Smem: Qs[64][68], Kt[64][68] (d-major), Vs[64][64], Ps[64][68].
// ---------------------------------------------------------------------------
#define QP 68
#define SMEM_ATTN ((64 * QP * 3 + 64 * 64) * 4)

__device__ __forceinline__ void dot_acc16(float* s, float q,
                                          const float* __restrict__ kr) {
    const float4 k0 = *(const float4*)kr;
    const float4 k1 = *(const float4*)(kr + 4);
    const float4 k2 = *(const float4*)(kr + 8);
    const float4 k3 = *(const float4*)(kr + 12);
    s[0]  += q * k0.x; s[1]  += q * k0.y; s[2]  += q * k0.z; s[3]  += q * k0.w;
    s[4]  += q * k1.x; s[5]  += q * k1.y; s[6]  += q * k1.z; s[7]  += q * k1.w;
    s[8]  += q * k2.x; s[9]  += q * k2.y; s[10] += q * k2.z; s[11] += q * k2.w;
    s[12] += q * k3.x; s[13] += q * k3.y; s[14] += q * k3.z; s[15] += q * k3.w;
}

__global__ __launch_bounds__(256)
void attn_kernel(const float* __restrict__ qkv, float* __restrict__ y)
{
    extern __shared__ float sm[];
    float* Qs = sm;                         // [64][QP]
    float* Kt = sm + 64 * QP;               // [64][QP]  Kt[d][j]
    float* Vs = sm + 2 * 64 * QP;           // [64][64]  Vs[j][d]
    float* Ps = sm + 2 * 64 * QP + 64 * 64; // [64][QP]

    const int qb  = blockIdx.x;
    const int b   = blockIdx.y >> 4;
    const int h   = blockIdx.y & 15;
    const int tid = threadIdx.x;
    const int ty  = tid >> 2;       // 0..63
    const int c4  = (tid & 3) << 4; // 0,16,32,48

    const float* base = qkv + (size_t)b * TDIM * QKVW + h * HD;

    // Load Q tile (pre-scaled by 1/sqrt(D) = 0.125)
    {
        const float* src = base + (size_t)(qb * 64 + ty) * QKVW + c4;
        float4* dst = (float4*)&Qs[ty * QP + c4];
#pragma unroll
        for (int q = 0; q < 4; q++) {
            float4 v = ((const float4*)src)[q];
            v.x *= 0.125f; v.y *= 0.125f; v.z *= 0.125f; v.w *= 0.125f;
            dst[q] = v;
        }
    }

    float m_i = -1e30f, l_i = 0.f;
    float o[16];
#pragma unroll
    for (int q = 0; q < 16; q++) o[q] = 0.f;

    for (int kb = 0; kb <= qb; kb++) {
        __syncthreads();
        // Load K (transposed d-major) and V tiles
        {
            const float* ks = base + CDIM     + (size_t)(kb * 64 + ty) * QKVW + c4;
            const float* vs = base + 2 * CDIM + (size_t)(kb * 64 + ty) * QKVW + c4;
#pragma unroll
            for (int q = 0; q < 4; q++) {
                const float4 kv = ((const float4*)ks)[q];
                const int d = c4 + q * 4;
                Kt[(d + 0) * QP + ty] = kv.x;
                Kt[(d + 1) * QP + ty] = kv.y;
                Kt[(d + 2) * QP + ty] = kv.z;
                Kt[(d + 3) * QP + ty] = kv.w;
                ((float4*)&Vs[ty * 64 + c4])[q] = ((const float4*)vs)[q];
            }
        }
        __syncthreads();

        // S = Q K^T (scaled)
        float s[16];
#pragma unroll
        for (int q = 0; q < 16; q++) s[q] = 0.f;
#pragma unroll 4
        for (int d = 0; d < 64; d++)
            dot_acc16(s, Qs[ty * QP + d], &Kt[d * QP + c4]);

        if (kb == qb) {
#pragma unroll
            for (int jj = 0; jj < 16; jj++)
                if (c4 + jj > ty) s[jj] = -1e30f;
        }

        // Online softmax (row split across 4 adjacent lanes)
        float mx = s[0];
#pragma unroll
        for (int jj = 1; jj < 16; jj++) mx = fmaxf(mx, s[jj]);
        mx = fmaxf(mx, __shfl_xor_sync(0xffffffffu, mx, 1));
        mx = fmaxf(mx, __shfl_xor_sync(0xffffffffu, mx, 2));
        const float m_new = fmaxf(m_i, mx);
        const float alpha = __expf(m_i - m_new);
        float p[16];
        float rsum = 0.f;
#pragma unroll
        for (int jj = 0; jj < 16; jj++) {
            p[jj] = __expf(s[jj] - m_new);
            rsum += p[jj];
        }
        rsum += __shfl_xor_sync(0xffffffffu, rsum, 1);
        rsum += __shfl_xor_sync(0xffffffffu, rsum, 2);
        l_i = l_i * alpha + rsum;
        m_i = m_new;
#pragma unroll
        for (int q = 0; q < 16; q++) o[q] *= alpha;

        // Stage P for the PV product (row owned by 4 lanes of one warp)
        float4* pd = (float4*)&Ps[ty * QP + c4];
        pd[0] = make_float4(p[0],  p[1],  p[2],  p[3]);
        pd[1] = make_float4(p[4],  p[5],  p[6],  p[7]);
        pd[2] = make_float4(p[8],  p[9],  p[10], p[11]);
        pd[3] = make_float4(p[12], p[13], p[14], p[15]);
        __syncwarp();

        // O += P V
#pragma unroll 4
        for (int j = 0; j < 64; j++)
            dot_acc16(o, Ps[ty * QP + j], &Vs[j * 64 + c4]);
    }

    const float inv = 1.0f / l_i;
    float* dst = y + (size_t)(b * TDIM + qb * 64 + ty) * CDIM + h * HD + c4;
#pragma unroll
    for (int q = 0; q < 16; q += 4) {
        *(float4*)(dst + q) =
            make_float4(o[q] * inv, o[q + 1] * inv, o[q + 2] * inv, o[q + 3] * inv);
    }
}

// ---------------------------------------------------------------------------
// Launch orchestration (graph-capturable: kernel launches only)
// ---------------------------------------------------------------------------
extern "C" void kernel_launch(void* const* d_in, const int* in_sizes, int n_in,
                              void* d_out, int out_size)
{
    const float* x      = (const float*)d_in[0];
    const float* g1     = (const float*)d_in[1];
    const float* w_qkv  = (const float*)d_in[2];
    const float* w_o    = (const float*)d_in[3];
    const float* g2     = (const float*)d_in[4];
    const float* w_fc   = (const float*)d_in[5];
    const float* w_proj = (const float*)d_in[6];
    float* out = (float*)d_out;

    float *ln, *qkvb, *yb, *x2, *hb;
    cudaGetSymbolAddress((void**)&ln,   g_ln);
    cudaGetSymbolAddress((void**)&qkvb, g_qkv);
    cudaGetSymbolAddress((void**)&yb,   g_y);
    cudaGetSymbolAddress((void**)&x2,   g_x2);
    cudaGetSymbolAddress((void**)&hb,   g_h);

    cudaFuncSetAttribute(attn_kernel,
                         cudaFuncAttributeMaxDynamicSharedMemorySize, SMEM_ATTN);

    // x1 = ln1(x);  qkv = x1 @ Wqkv^T
    ln_kernel<<<BT, 256>>>(x, g1, ln);
    sgemm_nt<0><<<dim3(QKVW / 128, BT / 128), 256>>>(ln, w_qkv, nullptr, qkvb,
                                                     BT, QKVW, CDIM);
    // y = causal_attention(q,k,v)
    attn_kernel<<<dim3(TDIM / 64, BDIM * HEADS), 256, SMEM_ATTN>>>(qkvb, yb);
    // x2 = x + y @ Wo^T
    sgemm_nt<1><<<dim3(CDIM / 128, BT / 128), 256>>>(yb, w_o, x, x2,
                                                     BT, CDIM, CDIM);
    // h = gelu(ln2(x2) @ Wfc^T)
    ln_kernel<<<BT, 256>>>(x2, g2, ln);
    sgemm_nt<2><<<dim3(FFDIM / 128, BT / 128), 256>>>(ln, w_fc, nullptr, hb,
                                                      BT, FFDIM, CDIM);
    // out = x2 + h @ Wproj^T
    sgemm_nt<1><<<dim3(CDIM / 128, BT / 128), 256>>>(hb, w_proj, x2, out,
                                                     BT, CDIM, FFDIM);
}

// round 3
// speedup vs baseline: 1.5485x; 1.5485x over previous
#include <cuda_runtime.h>
#include <math.h>
#include <stdint.h>

// Problem constants
#define BDIM   4
#define TDIM   2048
#define CDIM   1024
#define HEADS  16
#define HD     64
#define FFDIM  4096
#define BT     8192            // B*T rows
#define QKVW   3072            // 3*C

// ---------------------------------------------------------------------------
// Scratch (no allocations allowed — __device__ globals)
// ---------------------------------------------------------------------------
__device__ float g_ln [BT * CDIM];
__device__ float g_qkv[BT * QKVW];
__device__ float g_y  [BT * CDIM];
__device__ float g_x2 [BT * CDIM];
__device__ float g_h  [BT * FFDIM];

// ---------------------------------------------------------------------------
// Helpers
// ---------------------------------------------------------------------------
__device__ __forceinline__ uint32_t smem_u32(const void* p) {
    uint32_t a;
    asm("{ .reg .u64 t; cvta.to.shared.u64 t, %1; cvt.u32.u64 %0, t; }"
        : "=r"(a) : "l"(p));
    return a;
}
__device__ __forceinline__ uint32_t f2tf32(float f) {
    uint32_t u;
    asm("cvt.rna.tf32.f32 %0, %1;" : "=r"(u) : "f"(f));
    return u;
}
__device__ __forceinline__ void cp_async16(uint32_t saddr, const void* gaddr) {
    asm volatile("cp.async.cg.shared.global [%0], [%1], 16;"
                 :: "r"(saddr), "l"(gaddr) : "memory");
}
__device__ __forceinline__ void cp_commit() {
    asm volatile("cp.async.commit_group;" ::: "memory");
}
__device__ __forceinline__ void mma_tf32(float* d, const uint32_t* a,
                                         const uint32_t* b) {
    asm volatile(
        "mma.sync.aligned.m16n8k8.row.col.f32.tf32.tf32.f32 "
        "{%0,%1,%2,%3}, {%4,%5,%6,%7}, {%8,%9}, {%0,%1,%2,%3};"
        : "+f"(d[0]), "+f"(d[1]), "+f"(d[2]), "+f"(d[3])
        : "r"(a[0]), "r"(a[1]), "r"(a[2]), "r"(a[3]), "r"(b[0]), "r"(b[1]));
}
__device__ __forceinline__ float gelu_f(float v) {
    return 0.5f * v * (1.0f + erff(v * 0.70710678118654752f));
}

// ---------------------------------------------------------------------------
// LayerNorm: one block per row, C=1024, 256 threads x float4
// ---------------------------------------------------------------------------
__global__ __launch_bounds__(256)
void ln_kernel(const float* __restrict__ x, const float* __restrict__ g,
               float* __restrict__ y)
{
    const int row = blockIdx.x;
    const int tid = threadIdx.x;
    const float4 v = ((const float4*)(x + (size_t)row * CDIM))[tid];
    float s  = v.x + v.y + v.z + v.w;
    float ss = v.x * v.x + v.y * v.y + v.z * v.z + v.w * v.w;
#pragma unroll
    for (int o = 16; o > 0; o >>= 1) {
        s  += __shfl_xor_sync(0xffffffffu, s,  o);
        ss += __shfl_xor_sync(0xffffffffu, ss, o);
    }
    __shared__ float rs[8], rss[8];
    const int w = tid >> 5, lane = tid & 31;
    if (lane == 0) { rs[w] = s; rss[w] = ss; }
    __syncthreads();
    if (tid == 0) {
        float a = 0.f, b = 0.f;
#pragma unroll
        for (int i = 0; i < 8; i++) { a += rs[i]; b += rss[i]; }
        const float mean = a * (1.0f / CDIM);
        const float var  = b * (1.0f / CDIM) - mean * mean;
        rs[0]  = mean;
        rss[0] = rsqrtf(var + 1e-5f);
    }
    __syncthreads();
    const float mean = rs[0], rstd = rss[0];
    const float4 gv = ((const float4*)g)[tid];
    float4 o4;
    o4.x = (v.x - mean) * rstd * gv.x;
    o4.y = (v.y - mean) * rstd * gv.y;
    o4.z = (v.z - mean) * rstd * gv.z;
    o4.w = (v.w - mean) * rstd * gv.w;
    ((float4*)(y + (size_t)row * CDIM))[tid] = o4;
}

// ---------------------------------------------------------------------------
// TF32 mma.sync GEMM (NT): C[m,n] = sum_k A[m,k]*B[n,k]
// 128x128 CTA tile, K-chunk 32, cp.async double buffer, 8 warps in 2x4 grid,
// each warp computes 64x32 via m16n8k8 fragments.
// EPI: 0 none, 1 +res, 2 gelu.  M,N % 128 == 0, K % 32 == 0.
// ---------------------------------------------------------------------------
#define TSTRIDE 36                   // padded floats per row (conflict-free)
#define TILE_F  (128 * TSTRIDE)      // floats per operand tile buffer
#define GSMEM_BYTES (4 * TILE_F * 4) // A0,B0,A1,B1

template <int EPI>
__global__ __launch_bounds__(256, 2)
void gemm_mma(const float* __restrict__ A, const float* __restrict__ B,
              const float* __restrict__ res, float* __restrict__ C,
              int M, int N, int K)
{
    extern __shared__ float sm[];
    float* Abuf[2] = { sm,            sm + 2 * TILE_F };
    float* Bbuf[2] = { sm + TILE_F,   sm + 3 * TILE_F };
    const uint32_t sb = smem_u32(sm);

    const int tid = threadIdx.x;
    const int wid = tid >> 5, lid = tid & 31;
    const int gid = lid >> 2, tig = lid & 3;
    const int wm = wid & 1;          // 0..1 : 64-row slab
    const int wn = wid >> 1;         // 0..3 : 32-col slab
    const int bm = blockIdx.y << 7, bn = blockIdx.x << 7;

    // cp.async load map: each thread copies 4 x 16B per operand tile.
    const int lrow = tid >> 3;           // 0..31
    const int lcol = (tid & 7) << 2;     // float col 0,4,...,28
    const float* Ag[4]; const float* Bg[4];
    uint32_t sOff[4];                    // byte offset within a tile buffer
#pragma unroll
    for (int p = 0; p < 4; p++) {
        const int r = p * 32 + lrow;
        Ag[p] = A + (size_t)(bm + r) * K + lcol;
        Bg[p] = B + (size_t)(bn + r) * K + lcol;
        sOff[p] = (uint32_t)(r * TSTRIDE + lcol) * 4u;
    }
    const uint32_t aBufB[2] = { sb,                    sb + 2u * TILE_F * 4u };
    const uint32_t bBufB[2] = { sb + TILE_F * 4u,      sb + 3u * TILE_F * 4u };

    float acc[4][4][4];                  // [mf][nf][4]
#pragma unroll
    for (int i = 0; i < 4; i++)
#pragma unroll
        for (int j = 0; j < 4; j++)
#pragma unroll
            for (int q = 0; q < 4; q++) acc[i][j][q] = 0.f;

    const int nk = K >> 5;

    // Prologue: chunk 0 -> buffer 0
#pragma unroll
    for (int p = 0; p < 4; p++) {
        cp_async16(aBufB[0] + sOff[p], Ag[p]);
        cp_async16(bBufB[0] + sOff[p], Bg[p]);
    }
    cp_commit();

    for (int c = 0; c < nk; c++) {
        if (c + 1 < nk) {
            const int ko = (c + 1) << 5;
            const int nb = (c + 1) & 1;
#pragma unroll
            for (int p = 0; p < 4; p++) {
                cp_async16(aBufB[nb] + sOff[p], Ag[p] + ko);
                cp_async16(bBufB[nb] + sOff[p], Bg[p] + ko);
            }
            cp_commit();
            asm volatile("cp.async.wait_group 1;" ::: "memory");
        } else {
            asm volatile("cp.async.wait_group 0;" ::: "memory");
        }
        __syncthreads();

        const float* As = Abuf[c & 1];
        const float* Bs = Bbuf[c & 1];
#pragma unroll
        for (int ks = 0; ks < 4; ks++) {
            const int k0 = ks * 8;
            uint32_t afr[4][4], bfr[4][2];
#pragma unroll
            for (int mf = 0; mf < 4; mf++) {
                const int r = wm * 64 + mf * 16 + gid;
                afr[mf][0] = f2tf32(As[(r)     * TSTRIDE + k0 + tig]);
                afr[mf][1] = f2tf32(As[(r + 8) * TSTRIDE + k0 + tig]);
                afr[mf][2] = f2tf32(As[(r)     * TSTRIDE + k0 + tig + 4]);
                afr[mf][3] = f2tf32(As[(r + 8) * TSTRIDE + k0 + tig + 4]);
            }
#pragma unroll
            for (int nf = 0; nf < 4; nf++) {
                const int n = wn * 32 + nf * 8 + gid;
                bfr[nf][0] = f2tf32(Bs[n * TSTRIDE + k0 + tig]);
                bfr[nf][1] = f2tf32(Bs[n * TSTRIDE + k0 + tig + 4]);
            }
#pragma unroll
            for (int mf = 0; mf < 4; mf++)
#pragma unroll
                for (int nf = 0; nf < 4; nf++)
                    mma_tf32(acc[mf][nf], afr[mf], bfr[nf]);
        }
        __syncthreads();
    }

    // Epilogue: c0,c1 -> (row, col..col+1); c2,c3 -> (row+8, ...)
#pragma unroll
    for (int mf = 0; mf < 4; mf++) {
        const int row0 = bm + wm * 64 + mf * 16 + gid;
#pragma unroll
        for (int nf = 0; nf < 4; nf++) {
            const int col = bn + wn * 32 + nf * 8 + 2 * tig;
            float2 v0 = make_float2(acc[mf][nf][0], acc[mf][nf][1]);
            float2 v1 = make_float2(acc[mf][nf][2], acc[mf][nf][3]);
            const size_t i0 = (size_t)row0 * N + col;
            const size_t i1 = (size_t)(row0 + 8) * N + col;
            if (EPI == 1) {
                const float2 r0 = *(const float2*)(res + i0);
                const float2 r1 = *(const float2*)(res + i1);
                v0.x += r0.x; v0.y += r0.y;
                v1.x += r1.x; v1.y += r1.y;
            }
            if (EPI == 2) {
                v0.x = gelu_f(v0.x); v0.y = gelu_f(v0.y);
                v1.x = gelu_f(v1.x); v1.y = gelu_f(v1.y);
            }
            *(float2*)(C + i0) = v0;
            *(float2*)(C + i1) = v1;
        }
    }
}

// ---------------------------------------------------------------------------
// Flash attention (fp32, causal). Grid: (T/64, B*H). Block: 256 threads.
// ---------------------------------------------------------------------------
#define QP 68
#define SMEM_ATTN ((64 * QP * 3 + 64 * 64) * 4)

__device__ __forceinline__ void dot_acc16(float* s, float q,
                                          const float* __restrict__ kr) {
    const float4 k0 = *(const float4*)kr;
    const float4 k1 = *(const float4*)(kr + 4);
    const float4 k2 = *(const float4*)(kr + 8);
    const float4 k3 = *(const float4*)(kr + 12);
    s[0]  += q * k0.x; s[1]  += q * k0.y; s[2]  += q * k0.z; s[3]  += q * k0.w;
    s[4]  += q * k1.x; s[5]  += q * k1.y; s[6]  += q * k1.z; s[7]  += q * k1.w;
    s[8]  += q * k2.x; s[9]  += q * k2.y; s[10] += q * k2.z; s[11] += q * k2.w;
    s[12] += q * k3.x; s[13] += q * k3.y; s[14] += q * k3.z; s[15] += q * k3.w;
}

__global__ __launch_bounds__(256)
void attn_kernel(const float* __restrict__ qkv, float* __restrict__ y)
{
    extern __shared__ float smA[];
    float* Qs = smA;
    float* Kt = smA + 64 * QP;
    float* Vs = smA + 2 * 64 * QP;
    float* Ps = smA + 2 * 64 * QP + 64 * 64;

    const int qb  = blockIdx.x;
    const int b   = blockIdx.y >> 4;
    const int h   = blockIdx.y & 15;
    const int tid = threadIdx.x;
    const int ty  = tid >> 2;
    const int c4  = (tid & 3) << 4;

    const float* base = qkv + (size_t)b * TDIM * QKVW + h * HD;

    {
        const float* src = base + (size_t)(qb * 64 + ty) * QKVW + c4;
        float4* dst = (float4*)&Qs[ty * QP + c4];
#pragma unroll
        for (int q = 0; q < 4; q++) {
            float4 v = ((const float4*)src)[q];
            v.x *= 0.125f; v.y *= 0.125f; v.z *= 0.125f; v.w *= 0.125f;
            dst[q] = v;
        }
    }

    float m_i = -1e30f, l_i = 0.f;
    float o[16];
#pragma unroll
    for (int q = 0; q < 16; q++) o[q] = 0.f;

    for (int kb = 0; kb <= qb; kb++) {
        __syncthreads();
        {
            const float* ks = base + CDIM     + (size_t)(kb * 64 + ty) * QKVW + c4;
            const float* vs = base + 2 * CDIM + (size_t)(kb * 64 + ty) * QKVW + c4;
#pragma unroll
            for (int q = 0; q < 4; q++) {
                const float4 kv = ((const float4*)ks)[q];
                const int d = c4 + q * 4;
                Kt[(d + 0) * QP + ty] = kv.x;
                Kt[(d + 1) * QP + ty] = kv.y;
                Kt[(d + 2) * QP + ty] = kv.z;
                Kt[(d + 3) * QP + ty] = kv.w;
                ((float4*)&Vs[ty * 64 + c4])[q] = ((const float4*)vs)[q];
            }
        }
        __syncthreads();

        float s[16];
#pragma unroll
        for (int q = 0; q < 16; q++) s[q] = 0.f;
#pragma unroll 4
        for (int d = 0; d < 64; d++)
            dot_acc16(s, Qs[ty * QP + d], &Kt[d * QP + c4]);

        if (kb == qb) {
#pragma unroll
            for (int jj = 0; jj < 16; jj++)
                if (c4 + jj > ty) s[jj] = -1e30f;
        }

        float mx = s[0];
#pragma unroll
        for (int jj = 1; jj < 16; jj++) mx = fmaxf(mx, s[jj]);
        mx = fmaxf(mx, __shfl_xor_sync(0xffffffffu, mx, 1));
        mx = fmaxf(mx, __shfl_xor_sync(0xffffffffu, mx, 2));
        const float m_new = fmaxf(m_i, mx);
        const float alpha = __expf(m_i - m_new);
        float p[16];
        float rsum = 0.f;
#pragma unroll
        for (int jj = 0; jj < 16; jj++) {
            p[jj] = __expf(s[jj] - m_new);
            rsum += p[jj];
        }
        rsum += __shfl_xor_sync(0xffffffffu, rsum, 1);
        rsum += __shfl_xor_sync(0xffffffffu, rsum, 2);
        l_i = l_i * alpha + rsum;
        m_i = m_new;
#pragma unroll
        for (int q = 0; q < 16; q++) o[q] *= alpha;

        float4* pd = (float4*)&Ps[ty * QP + c4];
        pd[0] = make_float4(p[0],  p[1],  p[2],  p[3]);
        pd[1] = make_float4(p[4],  p[5],  p[6],  p[7]);
        pd[2] = make_float4(p[8],  p[9],  p[10], p[11]);
        pd[3] = make_float4(p[12], p[13], p[14], p[15]);
        __syncwarp();

#pragma unroll 4
        for (int j = 0; j < 64; j++)
            dot_acc16(o, Ps[ty * QP + j], &Vs[j * 64 + c4]);
    }

    const float inv = 1.0f / l_i;
    float* dst = y + (size_t)(b * TDIM + qb * 64 + ty) * CDIM + h * HD + c4;
#pragma unroll
    for (int q = 0; q < 16; q += 4) {
        *(float4*)(dst + q) =
            make_float4(o[q] * inv, o[q + 1] * inv, o[q + 2] * inv, o[q + 3] * inv);
    }
}

// ---------------------------------------------------------------------------
// Launch orchestration (graph-capturable)
// ---------------------------------------------------------------------------
extern "C" void kernel_launch(void* const* d_in, const int* in_sizes, int n_in,
                              void* d_out, int out_size)
{
    const float* x      = (const float*)d_in[0];
    const float* g1     = (const float*)d_in[1];
    const float* w_qkv  = (const float*)d_in[2];
    const float* w_o    = (const float*)d_in[3];
    const float* g2     = (const float*)d_in[4];
    const float* w_fc   = (const float*)d_in[5];
    const float* w_proj = (const float*)d_in[6];
    float* out = (float*)d_out;

    float *ln, *qkvb, *yb, *x2, *hb;
    cudaGetSymbolAddress((void**)&ln,   g_ln);
    cudaGetSymbolAddress((void**)&qkvb, g_qkv);
    cudaGetSymbolAddress((void**)&yb,   g_y);
    cudaGetSymbolAddress((void**)&x2,   g_x2);
    cudaGetSymbolAddress((void**)&hb,   g_h);

    cudaFuncSetAttribute(attn_kernel,
                         cudaFuncAttributeMaxDynamicSharedMemorySize, SMEM_ATTN);
    cudaFuncSetAttribute(gemm_mma<0>,
                         cudaFuncAttributeMaxDynamicSharedMemorySize, GSMEM_BYTES);
    cudaFuncSetAttribute(gemm_mma<1>,
                         cudaFuncAttributeMaxDynamicSharedMemorySize, GSMEM_BYTES);
    cudaFuncSetAttribute(gemm_mma<2>,
                         cudaFuncAttributeMaxDynamicSharedMemorySize, GSMEM_BYTES);

    // x1 = ln1(x); qkv = x1 @ Wqkv^T
    ln_kernel<<<BT, 256>>>(x, g1, ln);
    gemm_mma<0><<<dim3(QKVW / 128, BT / 128), 256, GSMEM_BYTES>>>(
        ln, w_qkv, nullptr, qkvb, BT, QKVW, CDIM);
    // y = causal attention
    attn_kernel<<<dim3(TDIM / 64, BDIM * HEADS), 256, SMEM_ATTN>>>(qkvb, yb);
    // x2 = x + y @ Wo^T
    gemm_mma<1><<<dim3(CDIM / 128, BT / 128), 256, GSMEM_BYTES>>>(
        yb, w_o, x, x2, BT, CDIM, CDIM);
    // h = gelu(ln2(x2) @ Wfc^T)
    ln_kernel<<<BT, 256>>>(x2, g2, ln);
    gemm_mma<2><<<dim3(FFDIM / 128, BT / 128), 256, GSMEM_BYTES>>>(
        ln, w_fc, nullptr, hb, BT, FFDIM, CDIM);
    // out = x2 + h @ Wproj^T
    gemm_mma<1><<<dim3(CDIM / 128, BT / 128), 256, GSMEM_BYTES>>>(
        hb, w_proj, x2, out, BT, CDIM, FFDIM);
}

// round 4
// speedup vs baseline: 3.7725x; 2.4361x over previous
#include <cuda_runtime.h>
#include <math.h>
#include <stdint.h>

// Problem constants
#define BDIM   4
#define TDIM   2048
#define CDIM   1024
#define HEADS  16
#define HD     64
#define FFDIM  4096
#define BT     8192            // B*T rows
#define QKVW   3072            // 3*C

// ---------------------------------------------------------------------------
// Scratch (no allocations allowed — __device__ globals)
// ---------------------------------------------------------------------------
__device__ float g_ln [BT * CDIM];
__device__ float g_qkv[BT * QKVW];
__device__ float g_y  [BT * CDIM];
__device__ float g_x2 [BT * CDIM];
__device__ float g_h  [BT * FFDIM];

// ---------------------------------------------------------------------------
// Helpers
// ---------------------------------------------------------------------------
__device__ __forceinline__ uint32_t smem_u32(const void* p) {
    uint32_t a;
    asm("{ .reg .u64 t; cvta.to.shared.u64 t, %1; cvt.u32.u64 %0, t; }"
        : "=r"(a) : "l"(p));
    return a;
}
__device__ __forceinline__ uint32_t f2tf32(float f) {
    uint32_t u;
    asm("cvt.rna.tf32.f32 %0, %1;" : "=r"(u) : "f"(f));
    return u;
}
__device__ __forceinline__ void cp_async16(uint32_t saddr, const void* gaddr) {
    asm volatile("cp.async.cg.shared.global [%0], [%1], 16;"
                 :: "r"(saddr), "l"(gaddr) : "memory");
}
__device__ __forceinline__ void cp_commit() {
    asm volatile("cp.async.commit_group;" ::: "memory");
}
__device__ __forceinline__ void mma_tf32(float* d, const uint32_t* a,
                                         const uint32_t* b) {
    asm volatile(
        "mma.sync.aligned.m16n8k8.row.col.f32.tf32.tf32.f32 "
        "{%0,%1,%2,%3}, {%4,%5,%6,%7}, {%8,%9}, {%0,%1,%2,%3};"
        : "+f"(d[0]), "+f"(d[1]), "+f"(d[2]), "+f"(d[3])
        : "r"(a[0]), "r"(a[1]), "r"(a[2]), "r"(a[3]), "r"(b[0]), "r"(b[1]));
}
__device__ __forceinline__ float gelu_f(float v) {
    return 0.5f * v * (1.0f + erff(v * 0.70710678118654752f));
}

// ---------------------------------------------------------------------------
// LayerNorm: one block per row, C=1024, 256 threads x float4
// ---------------------------------------------------------------------------
__global__ __launch_bounds__(256)
void ln_kernel(const float* __restrict__ x, const float* __restrict__ g,
               float* __restrict__ y)
{
    const int row = blockIdx.x;
    const int tid = threadIdx.x;
    const float4 v = ((const float4*)(x + (size_t)row * CDIM))[tid];
    float s  = v.x + v.y + v.z + v.w;
    float ss = v.x * v.x + v.y * v.y + v.z * v.z + v.w * v.w;
#pragma unroll
    for (int o = 16; o > 0; o >>= 1) {
        s  += __shfl_xor_sync(0xffffffffu, s,  o);
        ss += __shfl_xor_sync(0xffffffffu, ss, o);
    }
    __shared__ float rs[8], rss[8];
    const int w = tid >> 5, lane = tid & 31;
    if (lane == 0) { rs[w] = s; rss[w] = ss; }
    __syncthreads();
    if (tid == 0) {
        float a = 0.f, b = 0.f;
#pragma unroll
        for (int i = 0; i < 8; i++) { a += rs[i]; b += rss[i]; }
        const float mean = a * (1.0f / CDIM);
        const float var  = b * (1.0f / CDIM) - mean * mean;
        rs[0]  = mean;
        rss[0] = rsqrtf(var + 1e-5f);
    }
    __syncthreads();
    const float mean = rs[0], rstd = rss[0];
    const float4 gv = ((const float4*)g)[tid];
    float4 o4;
    o4.x = (v.x - mean) * rstd * gv.x;
    o4.y = (v.y - mean) * rstd * gv.y;
    o4.z = (v.z - mean) * rstd * gv.z;
    o4.w = (v.w - mean) * rstd * gv.w;
    ((float4*)(y + (size_t)row * CDIM))[tid] = o4;
}

// ---------------------------------------------------------------------------
// TF32 mma.sync GEMM (NT): C[m,n] = sum_k A[m,k]*B[n,k]   (unchanged from R3)
// ---------------------------------------------------------------------------
#define TSTRIDE 36
#define TILE_F  (128 * TSTRIDE)
#define GSMEM_BYTES (4 * TILE_F * 4)

template <int EPI>
__global__ __launch_bounds__(256, 2)
void gemm_mma(const float* __restrict__ A, const float* __restrict__ B,
              const float* __restrict__ res, float* __restrict__ C,
              int M, int N, int K)
{
    extern __shared__ float sm[];
    float* Abuf[2] = { sm,            sm + 2 * TILE_F };
    float* Bbuf[2] = { sm + TILE_F,   sm + 3 * TILE_F };
    const uint32_t sb = smem_u32(sm);

    const int tid = threadIdx.x;
    const int wid = tid >> 5, lid = tid & 31;
    const int gid = lid >> 2, tig = lid & 3;
    const int wm = wid & 1;
    const int wn = wid >> 1;
    const int bm = blockIdx.y << 7, bn = blockIdx.x << 7;

    const int lrow = tid >> 3;
    const int lcol = (tid & 7) << 2;
    const float* Ag[4]; const float* Bg[4];
    uint32_t sOff[4];
#pragma unroll
    for (int p = 0; p < 4; p++) {
        const int r = p * 32 + lrow;
        Ag[p] = A + (size_t)(bm + r) * K + lcol;
        Bg[p] = B + (size_t)(bn + r) * K + lcol;
        sOff[p] = (uint32_t)(r * TSTRIDE + lcol) * 4u;
    }
    const uint32_t aBufB[2] = { sb,               sb + 2u * TILE_F * 4u };
    const uint32_t bBufB[2] = { sb + TILE_F * 4u, sb + 3u * TILE_F * 4u };

    float acc[4][4][4];
#pragma unroll
    for (int i = 0; i < 4; i++)
#pragma unroll
        for (int j = 0; j < 4; j++)
#pragma unroll
            for (int q = 0; q < 4; q++) acc[i][j][q] = 0.f;

    const int nk = K >> 5;

#pragma unroll
    for (int p = 0; p < 4; p++) {
        cp_async16(aBufB[0] + sOff[p], Ag[p]);
        cp_async16(bBufB[0] + sOff[p], Bg[p]);
    }
    cp_commit();

    for (int c = 0; c < nk; c++) {
        if (c + 1 < nk) {
            const int ko = (c + 1) << 5;
            const int nb = (c + 1) & 1;
#pragma unroll
            for (int p = 0; p < 4; p++) {
                cp_async16(aBufB[nb] + sOff[p], Ag[p] + ko);
                cp_async16(bBufB[nb] + sOff[p], Bg[p] + ko);
            }
            cp_commit();
            asm volatile("cp.async.wait_group 1;" ::: "memory");
        } else {
            asm volatile("cp.async.wait_group 0;" ::: "memory");
        }
        __syncthreads();

        const float* As = Abuf[c & 1];
        const float* Bs = Bbuf[c & 1];
#pragma unroll
        for (int ks = 0; ks < 4; ks++) {
            const int k0 = ks * 8;
            uint32_t afr[4][4], bfr[4][2];
#pragma unroll
            for (int mf = 0; mf < 4; mf++) {
                const int r = wm * 64 + mf * 16 + gid;
                afr[mf][0] = f2tf32(As[(r)     * TSTRIDE + k0 + tig]);
                afr[mf][1] = f2tf32(As[(r + 8) * TSTRIDE + k0 + tig]);
                afr[mf][2] = f2tf32(As[(r)     * TSTRIDE + k0 + tig + 4]);
                afr[mf][3] = f2tf32(As[(r + 8) * TSTRIDE + k0 + tig + 4]);
            }
#pragma unroll
            for (int nf = 0; nf < 4; nf++) {
                const int n = wn * 32 + nf * 8 + gid;
                bfr[nf][0] = f2tf32(Bs[n * TSTRIDE + k0 + tig]);
                bfr[nf][1] = f2tf32(Bs[n * TSTRIDE + k0 + tig + 4]);
            }
#pragma unroll
            for (int mf = 0; mf < 4; mf++)
#pragma unroll
                for (int nf = 0; nf < 4; nf++)
                    mma_tf32(acc[mf][nf], afr[mf], bfr[nf]);
        }
        __syncthreads();
    }

#pragma unroll
    for (int mf = 0; mf < 4; mf++) {
        const int row0 = bm + wm * 64 + mf * 16 + gid;
#pragma unroll
        for (int nf = 0; nf < 4; nf++) {
            const int col = bn + wn * 32 + nf * 8 + 2 * tig;
            float2 v0 = make_float2(acc[mf][nf][0], acc[mf][nf][1]);
            float2 v1 = make_float2(acc[mf][nf][2], acc[mf][nf][3]);
            const size_t i0 = (size_t)row0 * N + col;
            const size_t i1 = (size_t)(row0 + 8) * N + col;
            if (EPI == 1) {
                const float2 r0 = *(const float2*)(res + i0);
                const float2 r1 = *(const float2*)(res + i1);
                v0.x += r0.x; v0.y += r0.y;
                v1.x += r1.x; v1.y += r1.y;
            }
            if (EPI == 2) {
                v0.x = gelu_f(v0.x); v0.y = gelu_f(v0.y);
                v1.x = gelu_f(v1.x); v1.y = gelu_f(v1.y);
            }
            *(float2*)(C + i0) = v0;
            *(float2*)(C + i1) = v1;
        }
    }
}

// ---------------------------------------------------------------------------
// Flash attention with tf32 mma.sync.
// Grid: (T/64, B*H), 128 threads (4 warps). Warp w owns query rows w*16..+15
// (one m16 slab). Smem tiles stride 68 floats (conflict-free fragment LDS).
//   Qs[64][68] row-major (pre-scaled by 1/8), Ks[64][68] row-major,
//   Vt[64][68] = V transposed (d-major), Ps[64][68] staged P.
// ---------------------------------------------------------------------------
#define AP 68
#define SMEM_ATTN (4 * 64 * AP * 4)

__global__ __launch_bounds__(128)
void attn_mma(const float* __restrict__ qkv, float* __restrict__ y)
{
    extern __shared__ float smA[];
    float* Qs = smA;
    float* Ks = smA + 64 * AP;
    float* Vt = smA + 2 * 64 * AP;
    float* Ps = smA + 3 * 64 * AP;

    const int qb   = gridDim.x - 1 - blockIdx.x;   // heavy tiles first
    const int b    = blockIdx.y >> 4;
    const int h    = blockIdx.y & 15;
    const int tid  = threadIdx.x;
    const int wid  = tid >> 5, lane = tid & 31;
    const int gid  = lane >> 2, tig = lane & 3;
    const int r0   = wid * 16 + gid;               // local query row (and r0+8)

    const float* base = qkv + (size_t)b * TDIM * QKVW + h * HD;

    // ---- load Q tile (scaled by 1/sqrt(64)=0.125) ----
    const int lr  = tid & 63;
    const int lch = (tid >> 6) << 5;    // 0 or 32
    {
        const float* src = base + (size_t)(qb * 64 + lr) * QKVW + lch;
        float* dst = &Qs[lr * AP + lch];
#pragma unroll
        for (int i = 0; i < 8; i++) {
            float4 v = ((const float4*)src)[i];
            v.x *= 0.125f; v.y *= 0.125f; v.z *= 0.125f; v.w *= 0.125f;
            *(float4*)(dst + 4 * i) = v;
        }
    }

    float oacc[8][4];
#pragma unroll
    for (int nf = 0; nf < 8; nf++)
#pragma unroll
        for (int q = 0; q < 4; q++) oacc[nf][q] = 0.f;
    float m0 = -1e30f, m1 = -1e30f, l0 = 0.f, l1 = 0.f;

    for (int kb = 0; kb <= qb; kb++) {
        __syncthreads();
        // ---- load K (row-major) and V (transposed) ----
        {
            const float* ksrc = base + CDIM     + (size_t)(kb * 64 + lr) * QKVW + lch;
            const float* vsrc = base + 2 * CDIM + (size_t)(kb * 64 + lr) * QKVW + lch;
#pragma unroll
            for (int i = 0; i < 8; i++) {
                *(float4*)&Ks[lr * AP + lch + 4 * i] = ((const float4*)ksrc)[i];
                const float4 vv = ((const float4*)vsrc)[i];
                const int d = lch + 4 * i;
                Vt[(d + 0) * AP + lr] = vv.x;
                Vt[(d + 1) * AP + lr] = vv.y;
                Vt[(d + 2) * AP + lr] = vv.z;
                Vt[(d + 3) * AP + lr] = vv.w;
            }
        }
        __syncthreads();

        // ---- S = Q K^T (16x64 per warp) ----
        float sacc[8][4];
#pragma unroll
        for (int nf = 0; nf < 8; nf++)
#pragma unroll
            for (int q = 0; q < 4; q++) sacc[nf][q] = 0.f;
#pragma unroll
        for (int ks = 0; ks < 8; ks++) {
            const int k0 = ks * 8;
            uint32_t a[4];
            a[0] = f2tf32(Qs[(r0)     * AP + k0 + tig]);
            a[1] = f2tf32(Qs[(r0 + 8) * AP + k0 + tig]);
            a[2] = f2tf32(Qs[(r0)     * AP + k0 + tig + 4]);
            a[3] = f2tf32(Qs[(r0 + 8) * AP + k0 + tig + 4]);
#pragma unroll
            for (int nf = 0; nf < 8; nf++) {
                uint32_t bb[2];
                bb[0] = f2tf32(Ks[(nf * 8 + gid) * AP + k0 + tig]);
                bb[1] = f2tf32(Ks[(nf * 8 + gid) * AP + k0 + tig + 4]);
                mma_tf32(sacc[nf], a, bb);
            }
        }

        // ---- causal mask on diagonal tile ----
        if (kb == qb) {
#pragma unroll
            for (int nf = 0; nf < 8; nf++) {
                const int c0 = nf * 8 + 2 * tig;
                if (c0     > r0)     sacc[nf][0] = -1e30f;
                if (c0 + 1 > r0)     sacc[nf][1] = -1e30f;
                if (c0     > r0 + 8) sacc[nf][2] = -1e30f;
                if (c0 + 1 > r0 + 8) sacc[nf][3] = -1e30f;
            }
        }

        // ---- online softmax (rows r0 and r0+8, reduce over tig lanes) ----
        float mx0 = -1e30f, mx1 = -1e30f;
#pragma unroll
        for (int nf = 0; nf < 8; nf++) {
            mx0 = fmaxf(mx0, fmaxf(sacc[nf][0], sacc[nf][1]));
            mx1 = fmaxf(mx1, fmaxf(sacc[nf][2], sacc[nf][3]));
        }
        mx0 = fmaxf(mx0, __shfl_xor_sync(0xffffffffu, mx0, 1));
        mx0 = fmaxf(mx0, __shfl_xor_sync(0xffffffffu, mx0, 2));
        mx1 = fmaxf(mx1, __shfl_xor_sync(0xffffffffu, mx1, 1));
        mx1 = fmaxf(mx1, __shfl_xor_sync(0xffffffffu, mx1, 2));
        const float mn0 = fmaxf(m0, mx0), mn1 = fmaxf(m1, mx1);
        const float al0 = __expf(m0 - mn0), al1 = __expf(m1 - mn1);
        float rs0 = 0.f, rs1 = 0.f;
#pragma unroll
        for (int nf = 0; nf < 8; nf++) {
            const float p0 = __expf(sacc[nf][0] - mn0);
            const float p1 = __expf(sacc[nf][1] - mn0);
            const float p2 = __expf(sacc[nf][2] - mn1);
            const float p3 = __expf(sacc[nf][3] - mn1);
            rs0 += p0 + p1;
            rs1 += p2 + p3;
            const int c = nf * 8 + 2 * tig;
            *(float2*)&Ps[(r0)     * AP + c] = make_float2(p0, p1);
            *(float2*)&Ps[(r0 + 8) * AP + c] = make_float2(p2, p3);
        }
        rs0 += __shfl_xor_sync(0xffffffffu, rs0, 1);
        rs0 += __shfl_xor_sync(0xffffffffu, rs0, 2);
        rs1 += __shfl_xor_sync(0xffffffffu, rs1, 1);
        rs1 += __shfl_xor_sync(0xffffffffu, rs1, 2);
        l0 = l0 * al0 + rs0;  m0 = mn0;
        l1 = l1 * al1 + rs1;  m1 = mn1;
#pragma unroll
        for (int nf = 0; nf < 8; nf++) {
            oacc[nf][0] *= al0; oacc[nf][1] *= al0;
            oacc[nf][2] *= al1; oacc[nf][3] *= al1;
        }
        __syncwarp();

        // ---- O += P V  (A = P rows [warp-exclusive], B = Vt) ----
#pragma unroll
        for (int ks = 0; ks < 8; ks++) {
            const int k0 = ks * 8;
            uint32_t a[4];
            a[0] = f2tf32(Ps[(r0)     * AP + k0 + tig]);
            a[1] = f2tf32(Ps[(r0 + 8) * AP + k0 + tig]);
            a[2] = f2tf32(Ps[(r0)     * AP + k0 + tig + 4]);
            a[3] = f2tf32(Ps[(r0 + 8) * AP + k0 + tig + 4]);
#pragma unroll
            for (int nf = 0; nf < 8; nf++) {
                uint32_t bb[2];
                bb[0] = f2tf32(Vt[(nf * 8 + gid) * AP + k0 + tig]);
                bb[1] = f2tf32(Vt[(nf * 8 + gid) * AP + k0 + tig + 4]);
                mma_tf32(oacc[nf], a, bb);
            }
        }
    }

    // ---- epilogue ----
    const float inv0 = 1.0f / l0, inv1 = 1.0f / l1;
    float* dst0 = y + (size_t)(b * TDIM + qb * 64 + r0) * CDIM + h * HD;
    float* dst1 = dst0 + 8 * CDIM;
#pragma unroll
    for (int nf = 0; nf < 8; nf++) {
        const int c = nf * 8 + 2 * tig;
        *(float2*)(dst0 + c) = make_float2(oacc[nf][0] * inv0, oacc[nf][1] * inv0);
        *(float2*)(dst1 + c) = make_float2(oacc[nf][2] * inv1, oacc[nf][3] * inv1);
    }
}

// ---------------------------------------------------------------------------
// Launch orchestration (graph-capturable)
// ---------------------------------------------------------------------------
extern "C" void kernel_launch(void* const* d_in, const int* in_sizes, int n_in,
                              void* d_out, int out_size)
{
    const float* x      = (const float*)d_in[0];
    const float* g1     = (const float*)d_in[1];
    const float* w_qkv  = (const float*)d_in[2];
    const float* w_o    = (const float*)d_in[3];
    const float* g2     = (const float*)d_in[4];
    const float* w_fc   = (const float*)d_in[5];
    const float* w_proj = (const float*)d_in[6];
    float* out = (float*)d_out;

    float *ln, *qkvb, *yb, *x2, *hb;
    cudaGetSymbolAddress((void**)&ln,   g_ln);
    cudaGetSymbolAddress((void**)&qkvb, g_qkv);
    cudaGetSymbolAddress((void**)&yb,   g_y);
    cudaGetSymbolAddress((void**)&x2,   g_x2);
    cudaGetSymbolAddress((void**)&hb,   g_h);

    cudaFuncSetAttribute(attn_mma,
                         cudaFuncAttributeMaxDynamicSharedMemorySize, SMEM_ATTN);
    cudaFuncSetAttribute(gemm_mma<0>,
                         cudaFuncAttributeMaxDynamicSharedMemorySize, GSMEM_BYTES);
    cudaFuncSetAttribute(gemm_mma<1>,
                         cudaFuncAttributeMaxDynamicSharedMemorySize, GSMEM_BYTES);
    cudaFuncSetAttribute(gemm_mma<2>,
                         cudaFuncAttributeMaxDynamicSharedMemorySize, GSMEM_BYTES);

    // x1 = ln1(x); qkv = x1 @ Wqkv^T
    ln_kernel<<<BT, 256>>>(x, g1, ln);
    gemm_mma<0><<<dim3(QKVW / 128, BT / 128), 256, GSMEM_BYTES>>>(
        ln, w_qkv, nullptr, qkvb, BT, QKVW, CDIM);
    // y = causal attention (tf32 mma)
    attn_mma<<<dim3(TDIM / 64, BDIM * HEADS), 128, SMEM_ATTN>>>(qkvb, yb);
    // x2 = x + y @ Wo^T
    gemm_mma<1><<<dim3(CDIM / 128, BT / 128), 256, GSMEM_BYTES>>>(
        yb, w_o, x, x2, BT, CDIM, CDIM);
    // h = gelu(ln2(x2) @ Wfc^T)
    ln_kernel<<<BT, 256>>>(x2, g2, ln);
    gemm_mma<2><<<dim3(FFDIM / 128, BT / 128), 256, GSMEM_BYTES>>>(
        ln, w_fc, nullptr, hb, BT, FFDIM, CDIM);
    // out = x2 + h @ Wproj^T
    gemm_mma<1><<<dim3(CDIM / 128, BT / 128), 256, GSMEM_BYTES>>>(
        hb, w_proj, x2, out, BT, CDIM, FFDIM);
}

// round 5
// speedup vs baseline: 4.4553x; 1.1810x over previous
#include <cuda_runtime.h>
#include <math.h>
#include <stdint.h>

// Problem constants
#define BDIM   4
#define TDIM   2048
#define CDIM   1024
#define HEADS  16
#define HD     64
#define FFDIM  4096
#define BT     8192            // B*T rows
#define QKVW   3072            // 3*C

// ---------------------------------------------------------------------------
// Scratch (no allocations allowed — __device__ globals)
// ---------------------------------------------------------------------------
__device__ float g_ln [BT * CDIM];
__device__ float g_qkv[BT * QKVW];
__device__ float g_y  [BT * CDIM];
__device__ float g_x2 [BT * CDIM];
__device__ float g_h  [BT * FFDIM];
// tf32-rounded weights
__device__ float g_wq [QKVW * CDIM];
__device__ float g_wo [CDIM * CDIM];
__device__ float g_wfc[FFDIM * CDIM];
__device__ float g_wp [CDIM * FFDIM];

// ---------------------------------------------------------------------------
// Helpers
// ---------------------------------------------------------------------------
__device__ __forceinline__ uint32_t smem_u32(const void* p) {
    uint32_t a;
    asm("{ .reg .u64 t; cvta.to.shared.u64 t, %1; cvt.u32.u64 %0, t; }"
        : "=r"(a) : "l"(p));
    return a;
}
__device__ __forceinline__ uint32_t f2tf32(float f) {
    uint32_t u;
    asm("cvt.rna.tf32.f32 %0, %1;" : "=r"(u) : "f"(f));
    return u;
}
__device__ __forceinline__ float tf32r(float f) {
    return __uint_as_float(f2tf32(f));
}
__device__ __forceinline__ void cp_async16(uint32_t saddr, const void* gaddr) {
    asm volatile("cp.async.cg.shared.global [%0], [%1], 16;"
                 :: "r"(saddr), "l"(gaddr) : "memory");
}
__device__ __forceinline__ void cp_commit() {
    asm volatile("cp.async.commit_group;" ::: "memory");
}
__device__ __forceinline__ void mma_tf32(float* d, const uint32_t* a,
                                         const uint32_t* b) {
    asm volatile(
        "mma.sync.aligned.m16n8k8.row.col.f32.tf32.tf32.f32 "
        "{%0,%1,%2,%3}, {%4,%5,%6,%7}, {%8,%9}, {%0,%1,%2,%3};"
        : "+f"(d[0]), "+f"(d[1]), "+f"(d[2]), "+f"(d[3])
        : "r"(a[0]), "r"(a[1]), "r"(a[2]), "r"(a[3]), "r"(b[0]), "r"(b[1]));
}
__device__ __forceinline__ float gelu_f(float v) {
    return 0.5f * v * (1.0f + erff(v * 0.70710678118654752f));
}

// ---------------------------------------------------------------------------
// Weight prep: round to tf32 once (values then pass through GEMM untouched)
// ---------------------------------------------------------------------------
__global__ __launch_bounds__(256)
void round_tf32_kernel(const float* __restrict__ src, float* __restrict__ dst,
                       int n4)
{
    const int i = blockIdx.x * blockDim.x + threadIdx.x;
    if (i < n4) {
        float4 v = ((const float4*)src)[i];
        v.x = tf32r(v.x); v.y = tf32r(v.y);
        v.z = tf32r(v.z); v.w = tf32r(v.w);
        ((float4*)dst)[i] = v;
    }
}

// ---------------------------------------------------------------------------
// LayerNorm: one block per row, C=1024, 256 threads x float4.
// Output rounded to tf32 (it is only consumed as a GEMM A operand).
// ---------------------------------------------------------------------------
__global__ __launch_bounds__(256)
void ln_kernel(const float* __restrict__ x, const float* __restrict__ g,
               float* __restrict__ y)
{
    const int row = blockIdx.x;
    const int tid = threadIdx.x;
    const float4 v = ((const float4*)(x + (size_t)row * CDIM))[tid];
    float s  = v.x + v.y + v.z + v.w;
    float ss = v.x * v.x + v.y * v.y + v.z * v.z + v.w * v.w;
#pragma unroll
    for (int o = 16; o > 0; o >>= 1) {
        s  += __shfl_xor_sync(0xffffffffu, s,  o);
        ss += __shfl_xor_sync(0xffffffffu, ss, o);
    }
    __shared__ float rs[8], rss[8];
    const int w = tid >> 5, lane = tid & 31;
    if (lane == 0) { rs[w] = s; rss[w] = ss; }
    __syncthreads();
    if (tid == 0) {
        float a = 0.f, b = 0.f;
#pragma unroll
        for (int i = 0; i < 8; i++) { a += rs[i]; b += rss[i]; }
        const float mean = a * (1.0f / CDIM);
        const float var  = b * (1.0f / CDIM) - mean * mean;
        rs[0]  = mean;
        rss[0] = rsqrtf(var + 1e-5f);
    }
    __syncthreads();
    const float mean = rs[0], rstd = rss[0];
    const float4 gv = ((const float4*)g)[tid];
    float4 o4;
    o4.x = tf32r((v.x - mean) * rstd * gv.x);
    o4.y = tf32r((v.y - mean) * rstd * gv.y);
    o4.z = tf32r((v.z - mean) * rstd * gv.z);
    o4.w = tf32r((v.w - mean) * rstd * gv.w);
    ((float4*)(y + (size_t)row * CDIM))[tid] = o4;
}

// ---------------------------------------------------------------------------
// TF32 mma.sync GEMM v2 (NT): C[m,n] = sum_k A[m,k]*B[n,k]
// CTA 128x128, 128 threads (4 warps in 2x2), warp tile 64x64 (mf=4, nf=8).
// K-chunk 32, cp.async double buffer. Inputs MUST be pre-rounded to tf32 —
// fragments are reinterpreted, no cvt in the inner loop.
// EPI: 0 = round(acc) [feeds another mma], 1 = acc + res, 2 = round(gelu(acc)).
// ---------------------------------------------------------------------------
#define GP     36
#define TILE_F (128 * GP)
#define GSMEM2 (4 * TILE_F * 4)

template <int EPI>
__global__ __launch_bounds__(128, 2)
void gemm_v2(const float* __restrict__ A, const float* __restrict__ B,
             const float* __restrict__ res, float* __restrict__ C,
             int M, int N, int K)
{
    extern __shared__ float sm[];
    const uint32_t sb = smem_u32(sm);

    const int tid  = threadIdx.x;
    const int wid  = tid >> 5, lane = tid & 31;
    const int gid  = lane >> 2, tig = lane & 3;
    const int wm   = (wid & 1) << 6;     // 0 / 64 row slab
    const int wn   = (wid >> 1) << 6;    // 0 / 64 col slab
    const int bm   = blockIdx.y << 7, bn = blockIdx.x << 7;

    // cp.async map: 8 x 16B per operand tile per thread
    const int lr = tid >> 3;             // 0..15
    const int lc = (tid & 7) << 2;       // 0,4,...,28
    const float* Ag = A + (size_t)(bm + lr) * K + lc;
    const float* Bg = B + (size_t)(bn + lr) * K + lc;
    uint32_t so[8];
#pragma unroll
    for (int p = 0; p < 8; p++)
        so[p] = (uint32_t)((p * 16 + lr) * GP + lc) * 4u;

    const uint32_t aB[2] = { sb,                     sb + 2u * TILE_F * 4u };
    const uint32_t bB[2] = { sb + TILE_F * 4u,       sb + 3u * TILE_F * 4u };
    const float* Abuf[2] = { sm,             sm + 2 * TILE_F };
    const float* Bbuf[2] = { sm + TILE_F,    sm + 3 * TILE_F };

    float acc[4][8][4];
#pragma unroll
    for (int i = 0; i < 4; i++)
#pragma unroll
        for (int j = 0; j < 8; j++)
#pragma unroll
            for (int q = 0; q < 4; q++) acc[i][j][q] = 0.f;

    const int nk = K >> 5;

#pragma unroll
    for (int p = 0; p < 8; p++) {
        cp_async16(aB[0] + so[p], Ag + (size_t)(p * 16) * K);
        cp_async16(bB[0] + so[p], Bg + (size_t)(p * 16) * K);
    }
    cp_commit();

    for (int c = 0; c < nk; c++) {
        if (c + 1 < nk) {
            const int ko = (c + 1) << 5;
            const int nb = (c + 1) & 1;
#pragma unroll
            for (int p = 0; p < 8; p++) {
                cp_async16(aB[nb] + so[p], Ag + (size_t)(p * 16) * K + ko);
                cp_async16(bB[nb] + so[p], Bg + (size_t)(p * 16) * K + ko);
            }
            cp_commit();
            asm volatile("cp.async.wait_group 1;" ::: "memory");
        } else {
            asm volatile("cp.async.wait_group 0;" ::: "memory");
        }
        __syncthreads();

        const float* As = Abuf[c & 1];
        const float* Bs = Bbuf[c & 1];
#pragma unroll
        for (int ks = 0; ks < 4; ks++) {
            const int k0 = ks * 8;
            uint32_t afr[4][4], bfr[8][2];
#pragma unroll
            for (int mf = 0; mf < 4; mf++) {
                const int r = wm + mf * 16 + gid;
                afr[mf][0] = __float_as_uint(As[(r)     * GP + k0 + tig]);
                afr[mf][1] = __float_as_uint(As[(r + 8) * GP + k0 + tig]);
                afr[mf][2] = __float_as_uint(As[(r)     * GP + k0 + tig + 4]);
                afr[mf][3] = __float_as_uint(As[(r + 8) * GP + k0 + tig + 4]);
            }
#pragma unroll
            for (int nf = 0; nf < 8; nf++) {
                const int n = wn + nf * 8 + gid;
                bfr[nf][0] = __float_as_uint(Bs[n * GP + k0 + tig]);
                bfr[nf][1] = __float_as_uint(Bs[n * GP + k0 + tig + 4]);
            }
#pragma unroll
            for (int mf = 0; mf < 4; mf++)
#pragma unroll
                for (int nf = 0; nf < 8; nf++)
                    mma_tf32(acc[mf][nf], afr[mf], bfr[nf]);
        }
        __syncthreads();
    }

#pragma unroll
    for (int mf = 0; mf < 4; mf++) {
        const int row0 = bm + wm + mf * 16 + gid;
#pragma unroll
        for (int nf = 0; nf < 8; nf++) {
            const int col = bn + wn + nf * 8 + 2 * tig;
            float2 v0 = make_float2(acc[mf][nf][0], acc[mf][nf][1]);
            float2 v1 = make_float2(acc[mf][nf][2], acc[mf][nf][3]);
            const size_t i0 = (size_t)row0 * N + col;
            const size_t i1 = (size_t)(row0 + 8) * N + col;
            if (EPI == 0) {
                v0.x = tf32r(v0.x); v0.y = tf32r(v0.y);
                v1.x = tf32r(v1.x); v1.y = tf32r(v1.y);
            }
            if (EPI == 1) {
                const float2 r0 = *(const float2*)(res + i0);
                const float2 r1 = *(const float2*)(res + i1);
                v0.x += r0.x; v0.y += r0.y;
                v1.x += r1.x; v1.y += r1.y;
            }
            if (EPI == 2) {
                v0.x = tf32r(gelu_f(v0.x)); v0.y = tf32r(gelu_f(v0.y));
                v1.x = tf32r(gelu_f(v1.x)); v1.y = tf32r(gelu_f(v1.y));
            }
            *(float2*)(C + i0) = v0;
            *(float2*)(C + i1) = v1;
        }
    }
}

// ---------------------------------------------------------------------------
// Flash attention with tf32 mma.sync (qkv is pre-rounded tf32 -> no cvt).
// Grid: (T/64, B*H), 128 threads (4 warps). Warp w owns query rows w*16..+15.
// ---------------------------------------------------------------------------
#define AP 68
#define SMEM_ATTN (4 * 64 * AP * 4)

__global__ __launch_bounds__(128)
void attn_mma(const float* __restrict__ qkv, float* __restrict__ y)
{
    extern __shared__ float smA[];
    float* Qs = smA;
    float* Ks = smA + 64 * AP;
    float* Vt = smA + 2 * 64 * AP;
    float* Ps = smA + 3 * 64 * AP;

    const int qb   = gridDim.x - 1 - blockIdx.x;   // heavy tiles first
    const int b    = blockIdx.y >> 4;
    const int h    = blockIdx.y & 15;
    const int tid  = threadIdx.x;
    const int wid  = tid >> 5, lane = tid & 31;
    const int gid  = lane >> 2, tig = lane & 3;
    const int r0   = wid * 16 + gid;

    const float* base = qkv + (size_t)b * TDIM * QKVW + h * HD;

    const int lr  = tid & 63;
    const int lch = (tid >> 6) << 5;
    {
        const float* src = base + (size_t)(qb * 64 + lr) * QKVW + lch;
        float* dst = &Qs[lr * AP + lch];
#pragma unroll
        for (int i = 0; i < 8; i++) {
            float4 v = ((const float4*)src)[i];
            v.x *= 0.125f; v.y *= 0.125f; v.z *= 0.125f; v.w *= 0.125f;
            *(float4*)(dst + 4 * i) = v;
        }
    }

    float oacc[8][4];
#pragma unroll
    for (int nf = 0; nf < 8; nf++)
#pragma unroll
        for (int q = 0; q < 4; q++) oacc[nf][q] = 0.f;
    float m0 = -1e30f, m1 = -1e30f, l0 = 0.f, l1 = 0.f;

    for (int kb = 0; kb <= qb; kb++) {
        __syncthreads();
        {
            const float* ksrc = base + CDIM     + (size_t)(kb * 64 + lr) * QKVW + lch;
            const float* vsrc = base + 2 * CDIM + (size_t)(kb * 64 + lr) * QKVW + lch;
#pragma unroll
            for (int i = 0; i < 8; i++) {
                *(float4*)&Ks[lr * AP + lch + 4 * i] = ((const float4*)ksrc)[i];
                const float4 vv = ((const float4*)vsrc)[i];
                const int d = lch + 4 * i;
                Vt[(d + 0) * AP + lr] = vv.x;
                Vt[(d + 1) * AP + lr] = vv.y;
                Vt[(d + 2) * AP + lr] = vv.z;
                Vt[(d + 3) * AP + lr] = vv.w;
            }
        }
        __syncthreads();

        float sacc[8][4];
#pragma unroll
        for (int nf = 0; nf < 8; nf++)
#pragma unroll
            for (int q = 0; q < 4; q++) sacc[nf][q] = 0.f;
#pragma unroll
        for (int ks = 0; ks < 8; ks++) {
            const int k0 = ks * 8;
            uint32_t a[4];
            a[0] = __float_as_uint(Qs[(r0)     * AP + k0 + tig]);
            a[1] = __float_as_uint(Qs[(r0 + 8) * AP + k0 + tig]);
            a[2] = __float_as_uint(Qs[(r0)     * AP + k0 + tig + 4]);
            a[3] = __float_as_uint(Qs[(r0 + 8) * AP + k0 + tig + 4]);
#pragma unroll
            for (int nf = 0; nf < 8; nf++) {
                uint32_t bb[2];
                bb[0] = __float_as_uint(Ks[(nf * 8 + gid) * AP + k0 + tig]);
                bb[1] = __float_as_uint(Ks[(nf * 8 + gid) * AP + k0 + tig + 4]);
                mma_tf32(sacc[nf], a, bb);
            }
        }

        if (kb == qb) {
#pragma unroll
            for (int nf = 0; nf < 8; nf++) {
                const int c0 = nf * 8 + 2 * tig;
                if (c0     > r0)     sacc[nf][0] = -1e30f;
                if (c0 + 1 > r0)     sacc[nf][1] = -1e30f;
                if (c0     > r0 + 8) sacc[nf][2] = -1e30f;
                if (c0 + 1 > r0 + 8) sacc[nf][3] = -1e30f;
            }
        }

        float mx0 = -1e30f, mx1 = -1e30f;
#pragma unroll
        for (int nf = 0; nf < 8; nf++) {
            mx0 = fmaxf(mx0, fmaxf(sacc[nf][0], sacc[nf][1]));
            mx1 = fmaxf(mx1, fmaxf(sacc[nf][2], sacc[nf][3]));
        }
        mx0 = fmaxf(mx0, __shfl_xor_sync(0xffffffffu, mx0, 1));
        mx0 = fmaxf(mx0, __shfl_xor_sync(0xffffffffu, mx0, 2));
        mx1 = fmaxf(mx1, __shfl_xor_sync(0xffffffffu, mx1, 1));
        mx1 = fmaxf(mx1, __shfl_xor_sync(0xffffffffu, mx1, 2));
        const float mn0 = fmaxf(m0, mx0), mn1 = fmaxf(m1, mx1);
        const float al0 = __expf(m0 - mn0), al1 = __expf(m1 - mn1);
        float rs0 = 0.f, rs1 = 0.f;
#pragma unroll
        for (int nf = 0; nf < 8; nf++) {
            const float p0 = tf32r(__expf(sacc[nf][0] - mn0));
            const float p1 = tf32r(__expf(sacc[nf][1] - mn0));
            const float p2 = tf32r(__expf(sacc[nf][2] - mn1));
            const float p3 = tf32r(__expf(sacc[nf][3] - mn1));
            rs0 += p0 + p1;
            rs1 += p2 + p3;
            const int c = nf * 8 + 2 * tig;
            *(float2*)&Ps[(r0)     * AP + c] = make_float2(p0, p1);
            *(float2*)&Ps[(r0 + 8) * AP + c] = make_float2(p2, p3);
        }
        rs0 += __shfl_xor_sync(0xffffffffu, rs0, 1);
        rs0 += __shfl_xor_sync(0xffffffffu, rs0, 2);
        rs1 += __shfl_xor_sync(0xffffffffu, rs1, 1);
        rs1 += __shfl_xor_sync(0xffffffffu, rs1, 2);
        l0 = l0 * al0 + rs0;  m0 = mn0;
        l1 = l1 * al1 + rs1;  m1 = mn1;
#pragma unroll
        for (int nf = 0; nf < 8; nf++) {
            oacc[nf][0] *= al0; oacc[nf][1] *= al0;
            oacc[nf][2] *= al1; oacc[nf][3] *= al1;
        }
        __syncwarp();

#pragma unroll
        for (int ks = 0; ks < 8; ks++) {
            const int k0 = ks * 8;
            uint32_t a[4];
            a[0] = __float_as_uint(Ps[(r0)     * AP + k0 + tig]);
            a[1] = __float_as_uint(Ps[(r0 + 8) * AP + k0 + tig]);
            a[2] = __float_as_uint(Ps[(r0)     * AP + k0 + tig + 4]);
            a[3] = __float_as_uint(Ps[(r0 + 8) * AP + k0 + tig + 4]);
#pragma unroll
            for (int nf = 0; nf < 8; nf++) {
                uint32_t bb[2];
                bb[0] = __float_as_uint(Vt[(nf * 8 + gid) * AP + k0 + tig]);
                bb[1] = __float_as_uint(Vt[(nf * 8 + gid) * AP + k0 + tig + 4]);
                mma_tf32(oacc[nf], a, bb);
            }
        }
    }

    // epilogue: round (y feeds the O-proj mma as an A operand)
    const float inv0 = 1.0f / l0, inv1 = 1.0f / l1;
    float* dst0 = y + (size_t)(b * TDIM + qb * 64 + r0) * CDIM + h * HD;
    float* dst1 = dst0 + 8 * CDIM;
#pragma unroll
    for (int nf = 0; nf < 8; nf++) {
        const int c = nf * 8 + 2 * tig;
        *(float2*)(dst0 + c) = make_float2(tf32r(oacc[nf][0] * inv0),
                                           tf32r(oacc[nf][1] * inv0));
        *(float2*)(dst1 + c) = make_float2(tf32r(oacc[nf][2] * inv1),
                                           tf32r(oacc[nf][3] * inv1));
    }
}

// ---------------------------------------------------------------------------
// Launch orchestration (graph-capturable)
// ---------------------------------------------------------------------------
extern "C" void kernel_launch(void* const* d_in, const int* in_sizes, int n_in,
                              void* d_out, int out_size)
{
    const float* x      = (const float*)d_in[0];
    const float* g1     = (const float*)d_in[1];
    const float* w_qkv  = (const float*)d_in[2];
    const float* w_o    = (const float*)d_in[3];
    const float* g2     = (const float*)d_in[4];
    const float* w_fc   = (const float*)d_in[5];
    const float* w_proj = (const float*)d_in[6];
    float* out = (float*)d_out;

    float *ln, *qkvb, *yb, *x2, *hb, *wq, *wo, *wfc, *wp;
    cudaGetSymbolAddress((void**)&ln,   g_ln);
    cudaGetSymbolAddress((void**)&qkvb, g_qkv);
    cudaGetSymbolAddress((void**)&yb,   g_y);
    cudaGetSymbolAddress((void**)&x2,   g_x2);
    cudaGetSymbolAddress((void**)&hb,   g_h);
    cudaGetSymbolAddress((void**)&wq,   g_wq);
    cudaGetSymbolAddress((void**)&wo,   g_wo);
    cudaGetSymbolAddress((void**)&wfc,  g_wfc);
    cudaGetSymbolAddress((void**)&wp,   g_wp);

    cudaFuncSetAttribute(attn_mma,
                         cudaFuncAttributeMaxDynamicSharedMemorySize, SMEM_ATTN);
    cudaFuncSetAttribute(gemm_v2<0>,
                         cudaFuncAttributeMaxDynamicSharedMemorySize, GSMEM2);
    cudaFuncSetAttribute(gemm_v2<1>,
                         cudaFuncAttributeMaxDynamicSharedMemorySize, GSMEM2);
    cudaFuncSetAttribute(gemm_v2<2>,
                         cudaFuncAttributeMaxDynamicSharedMemorySize, GSMEM2);

    // Round weights to tf32 once per launch
    round_tf32_kernel<<<(QKVW * CDIM / 4 + 255) / 256, 256>>>(w_qkv, wq,
                                                              QKVW * CDIM / 4);
    round_tf32_kernel<<<(CDIM * CDIM / 4 + 255) / 256, 256>>>(w_o, wo,
                                                              CDIM * CDIM / 4);
    round_tf32_kernel<<<(FFDIM * CDIM / 4 + 255) / 256, 256>>>(w_fc, wfc,
                                                               FFDIM * CDIM / 4);
    round_tf32_kernel<<<(CDIM * FFDIM / 4 + 255) / 256, 256>>>(w_proj, wp,
                                                               CDIM * FFDIM / 4);

    // x1 = ln1(x); qkv = x1 @ Wqkv^T  (output rounded)
    ln_kernel<<<BT, 256>>>(x, g1, ln);
    gemm_v2<0><<<dim3(QKVW / 128, BT / 128), 128, GSMEM2>>>(
        ln, wq, nullptr, qkvb, BT, QKVW, CDIM);
    // y = causal attention (tf32 mma; output rounded)
    attn_mma<<<dim3(TDIM / 64, BDIM * HEADS), 128, SMEM_ATTN>>>(qkvb, yb);
    // x2 = x + y @ Wo^T
    gemm_v2<1><<<dim3(CDIM / 128, BT / 128), 128, GSMEM2>>>(
        yb, wo, x, x2, BT, CDIM, CDIM);
    // h = gelu(ln2(x2) @ Wfc^T)  (output rounded)
    ln_kernel<<<BT, 256>>>(x2, g2, ln);
    gemm_v2<2><<<dim3(FFDIM / 128, BT / 128), 128, GSMEM2>>>(
        ln, wfc, nullptr, hb, BT, FFDIM, CDIM);
    // out = x2 + h @ Wproj^T
    gemm_v2<1><<<dim3(CDIM / 128, BT / 128), 128, GSMEM2>>>(
        hb, wp, x2, out, BT, CDIM, FFDIM);
}